// round 10
// baseline (speedup 1.0000x reference)
#include <cuda_runtime.h>
#include <cuda_bf16.h>
#include <cstdint>

#define TT 1024
#define BX 128
#define NIJ (BX * BX)
#define NCHUNK 146       // block 0: steps [0,8); block b>0: [7b+1, 7b+8)
#define BUFB 102400      // one double-buffer slot: A(51200) + B(51200) bytes

// scratch: local prefix products, layout [t][i*128+j]; 64 MB
__device__ float g_scratch[TT * NIJ];

__device__ __forceinline__ uint32_t smem_u32(const void* p) {
    uint32_t a;
    asm("{ .reg .u64 t; cvta.to.shared.u64 t, %1; cvt.u32.u64 %0, t; }"
        : "=r"(a) : "l"(p));
    return a;
}
__device__ __forceinline__ void ldsm_x4(uint32_t& r0, uint32_t& r1,
                                        uint32_t& r2, uint32_t& r3,
                                        uint32_t addr) {
    asm volatile("ldmatrix.sync.aligned.m8n8.x4.shared.b16 {%0,%1,%2,%3}, [%4];"
                 : "=r"(r0), "=r"(r1), "=r"(r2), "=r"(r3) : "r"(addr));
}
__device__ __forceinline__ void mma16816(float* c, const uint32_t* a,
                                         uint32_t b0, uint32_t b1) {
    asm volatile(
        "mma.sync.aligned.m16n8k16.row.col.f32.bf16.bf16.f32 "
        "{%0,%1,%2,%3}, {%4,%5,%6,%7}, {%8,%9}, {%0,%1,%2,%3};"
        : "+f"(c[0]), "+f"(c[1]), "+f"(c[2]), "+f"(c[3])
        : "r"(a[0]), "r"(a[1]), "r"(a[2]), "r"(a[3]), "r"(b0), "r"(b1));
}
__device__ __forceinline__ uint32_t bcat(__nv_bfloat16 a, __nv_bfloat16 b) {
    __nv_bfloat162 t = __halves2bfloat162(a, b);
    return *reinterpret_cast<uint32_t*>(&t);
}

__device__ __forceinline__ void load_diffs(const float4* __restrict__ X4,
                                           const float4* __restrict__ Y4,
                                           int gbase, int s,
                                           float* fx, float* fy) {
    const int gb = gbase + s * 16;
#pragma unroll
    for (int c = 0; c < 4; ++c) {
        float4 a0 = X4[gb + c], a1 = X4[gb + 16 + c];
        fx[4 * c + 0] = (a1.x - a0.x) * 1023.0f;
        fx[4 * c + 1] = (a1.y - a0.y) * 1023.0f;
        fx[4 * c + 2] = (a1.z - a0.z) * 1023.0f;
        fx[4 * c + 3] = (a1.w - a0.w) * 1023.0f;
        float4 b0 = Y4[gb + c], b1 = Y4[gb + 16 + c];
        fy[4 * c + 0] = b1.x - b0.x;
        fy[4 * c + 1] = b1.y - b0.y;
        fy[4 * c + 2] = b1.z - b0.z;
        fy[4 * c + 3] = b1.w - b0.w;
    }
}

// Phase 1 (HMMA, pipelined): per step, Z = (1023 dX) dY^T via bf16-split
// K=192 concat A=[Xhi|Xhi|Xlo], B=[Yhi|Ylo|Yhi]. Double-buffered smem tiles,
// next-step diffs prefetched into registers, ONE barrier per step.
__global__ __launch_bounds__(512, 1)
void nsk_phase1(const float4* __restrict__ X4, const float4* __restrict__ Y4) {
    extern __shared__ char smc[];
    const uint32_t sb = smem_u32(smc);

    const int tid = threadIdx.x;
    const int wid = tid >> 5;
    const int lane = tid & 31;

    // conversion role
    const int crow = tid >> 2;           // 0..127
    const int cq = tid & 3;              // d-quad of 16
    const int gbase = crow * 16384 + cq * 4;
    // mma tile role
    const int m0 = (wid >> 2) * 32;
    const int n0 = (wid & 3) * 32;
    const int grp = lane >> 3, lrow = lane & 7;
    const uint32_t offA = (uint32_t)((lrow + 8 * (grp & 1)) * 400 + 16 * (grp >> 1));
    const uint32_t offB = (uint32_t)((lrow + 8 * (grp >> 1)) * 400 + 16 * (grp & 1));
    const int g = lane >> 2, tg = lane & 3;

    const int b = blockIdx.x;
    const int s_start = (b == 0) ? 0 : 7 * b + 1;
    const int s_end = 7 * b + 8;         // max 1023 at b=145

    float k[2][4][4];
#pragma unroll
    for (int a = 0; a < 2; a++)
#pragma unroll
        for (int c = 0; c < 4; c++)
#pragma unroll
            for (int e = 0; e < 4; e++) k[a][c][e] = 1.0f;

    float fx[16], fy[16];
    load_diffs(X4, Y4, gbase, s_start, fx, fy);   // prologue prefetch

    int p = 0;
    for (int s = s_start; s < s_end; ++s) {
        // ---- convert prefetched diffs -> bf16 hi/lo, STS into buffer p
        {
            uint32_t xh[8], xl[8], yh[8], yl[8];
#pragma unroll
            for (int m = 0; m < 8; ++m) {
                float u = fx[2 * m], v = fx[2 * m + 1];
                __nv_bfloat16 uh = __float2bfloat16_rn(u);
                __nv_bfloat16 vh = __float2bfloat16_rn(v);
                xh[m] = bcat(uh, vh);
                xl[m] = bcat(__float2bfloat16_rn(u - __bfloat162float(uh)),
                             __float2bfloat16_rn(v - __bfloat162float(vh)));
                float pp = fy[2 * m], q = fy[2 * m + 1];
                __nv_bfloat16 ph = __float2bfloat16_rn(pp);
                __nv_bfloat16 qh = __float2bfloat16_rn(q);
                yh[m] = bcat(ph, qh);
                yl[m] = bcat(__float2bfloat16_rn(pp - __bfloat162float(ph)),
                             __float2bfloat16_rn(q - __bfloat162float(qh)));
            }
            char* bufc = smc + p * BUFB;
            char* pa = bufc + crow * 400 + cq * 32;
            ((uint4*)pa)[0] = ((uint4*)xh)[0];
            ((uint4*)(pa + 16))[0] = ((uint4*)xh)[1];
            ((uint4*)(pa + 128))[0] = ((uint4*)xh)[0];      // Xhi copy 2
            ((uint4*)(pa + 144))[0] = ((uint4*)xh)[1];
            ((uint4*)(pa + 256))[0] = ((uint4*)xl)[0];      // Xlo
            ((uint4*)(pa + 272))[0] = ((uint4*)xl)[1];
            char* pb = bufc + 51200 + crow * 400 + cq * 32;
            ((uint4*)pb)[0] = ((uint4*)yh)[0];              // Yhi
            ((uint4*)(pb + 16))[0] = ((uint4*)yh)[1];
            ((uint4*)(pb + 128))[0] = ((uint4*)yl)[0];      // Ylo
            ((uint4*)(pb + 144))[0] = ((uint4*)yl)[1];
            ((uint4*)(pb + 256))[0] = ((uint4*)yh)[0];      // Yhi copy 2
            ((uint4*)(pb + 272))[0] = ((uint4*)yh)[1];
        }

        // ---- prefetch next step's diffs (hidden behind sync + MMA)
        if (s + 1 < s_end) load_diffs(X4, Y4, gbase, s + 1, fx, fy);

        __syncthreads();   // buffer p tiles visible; prior readers of p done (sync s-1)

        // ---- 12 k-chunks of 16 over K=192
        const uint32_t aA = sb + p * BUFB;
        const uint32_t aB = aA + 51200;
        float cacc[2][4][4];
#pragma unroll
        for (int mf = 0; mf < 2; mf++)
#pragma unroll
            for (int nf = 0; nf < 4; nf++)
#pragma unroll
                for (int e = 0; e < 4; e++) cacc[mf][nf][e] = 0.0f;

#pragma unroll
        for (int kc = 0; kc < 12; ++kc) {
            const uint32_t kb = kc * 32;
            uint32_t af0[4], af1[4], b0r[4], b1r[4];
            ldsm_x4(af0[0], af0[1], af0[2], af0[3], aA + m0 * 400 + kb + offA);
            ldsm_x4(af1[0], af1[1], af1[2], af1[3], aA + (m0 + 16) * 400 + kb + offA);
            ldsm_x4(b0r[0], b0r[1], b0r[2], b0r[3], aB + n0 * 400 + kb + offB);
            ldsm_x4(b1r[0], b1r[1], b1r[2], b1r[3], aB + (n0 + 16) * 400 + kb + offB);
            mma16816(cacc[0][0], af0, b0r[0], b0r[1]);
            mma16816(cacc[0][1], af0, b0r[2], b0r[3]);
            mma16816(cacc[0][2], af0, b1r[0], b1r[1]);
            mma16816(cacc[0][3], af0, b1r[2], b1r[3]);
            mma16816(cacc[1][0], af1, b0r[0], b0r[1]);
            mma16816(cacc[1][1], af1, b0r[2], b0r[3]);
            mma16816(cacc[1][2], af1, b1r[0], b1r[1]);
            mma16816(cacc[1][3], af1, b1r[2], b1r[3]);
        }

        // ---- epilogue: k *= (1+z); float2 stores, scratch[t][i*128+j]
        float* base = g_scratch + (size_t)(s + 1) * NIJ;
#pragma unroll
        for (int mf = 0; mf < 2; mf++) {
#pragma unroll
            for (int nf = 0; nf < 4; nf++) {
                const int i0 = m0 + mf * 16 + g;
                const int j = n0 + nf * 8 + tg * 2;
                float* c4 = cacc[mf][nf];
                float* kk = k[mf][nf];
                float k0 = fmaf(c4[0], kk[0], kk[0]);
                float k1 = fmaf(c4[1], kk[1], kk[1]);
                float k2 = fmaf(c4[2], kk[2], kk[2]);
                float k3 = fmaf(c4[3], kk[3], kk[3]);
                kk[0] = k0; kk[1] = k1; kk[2] = k2; kk[3] = k3;
                *(float2*)(base + i0 * BX + j) = make_float2(k0, k1);
                *(float2*)(base + (i0 + 8) * BX + j) = make_float2(k2, k3);
            }
        }
        p ^= 1;
    }
}

// Phase 2 (fused): one block per 32-ij strip. Chunk c's last written t is
// e = 7c+8 (c=0 wrote [1,8], c>0 wrote [7c+2, 7c+8]); owner of t>=1 is
// c = (t-2)/7 (C trunc division; t=1 -> 0).
__global__ __launch_bounds__(256, 8)
void nsk_phase2f(float* __restrict__ out) {
    extern __shared__ float sm[];
    float* cend = sm;                    // [146][32] -> exclusive scales
    float* qp = sm + NCHUNK * 32;        // [8][32]
    float* tile = qp + 8 * 32;           // [64][33]

    const int tid = threadIdx.x;
    const int lane = tid & 31;
    const int q = tid >> 5;              // 0..7
    const int lane64 = tid & 63;
    const int colg = tid >> 6;           // 0..3
    const int ij0 = blockIdx.x * 32;

    // A1: load chunk-end values
#pragma unroll
    for (int cc = 0; cc < 19; cc++) {
        const int c = q + 8 * cc;
        if (c < NCHUNK) {
            const int e = 7 * c + 8;
            cend[c * 32 + lane] = g_scratch[(size_t)e * NIJ + ij0 + lane];
        }
    }
    __syncthreads();

    // A2: 8 sub-scans of 19 chunks (guarded)
    {
        float p = 1.0f;
#pragma unroll 1
        for (int cc = 0; cc < 19; cc++) {
            const int c = 19 * q + cc;
            if (c < NCHUNK) {
                const float v = cend[c * 32 + lane];
                cend[c * 32 + lane] = p;
                p *= v;
            }
        }
        qp[q * 32 + lane] = p;
    }
    __syncthreads();

    // A3: fold in sub-scan offsets
    if (q > 0) {
        float off = qp[lane];
#pragma unroll
        for (int w = 1; w < 7; w++)
            if (q > w) off *= qp[w * 32 + lane];
#pragma unroll 1
        for (int cc = 0; cc < 19; cc++) {
            const int c = 19 * q + cc;
            if (c < NCHUNK) cend[c * 32 + lane] *= off;
        }
    }
    __syncthreads();

    // B: 16 tiles of 64 t-rows x 32 ij
#pragma unroll 1
    for (int ti = 0; ti < 16; ti++) {
        const int t0 = ti * 64;
#pragma unroll
        for (int rr = 0; rr < 8; rr++) {
            const int r = q + 8 * rr;
            const int t = t0 + r;
            if (t == 0) {
                tile[r * 33 + lane] = 1.0f;
            } else {
                const int c = (t - 2) / 7;   // t=1 -> 0 (trunc toward zero)
                const float v = g_scratch[(size_t)t * NIJ + ij0 + lane];
                tile[r * 33 + lane] = v * cend[c * 32 + lane];
            }
        }
        __syncthreads();
#pragma unroll
        for (int cc = 0; cc < 8; cc++) {
            const int col = colg + 4 * cc;
            out[(size_t)(ij0 + col) * TT + t0 + lane64] = tile[lane64 * 33 + col];
        }
        __syncthreads();
    }
}

extern "C" void kernel_launch(void* const* d_in, const int* in_sizes, int n_in,
                              void* d_out, int out_size) {
    const float4* X4 = (const float4*)d_in[0];
    const float4* Y4 = (const float4*)d_in[1];
    float* out = (float*)d_out;

    const int smem1 = 2 * BUFB;                                               // 204800 B
    const int smem2 = (NCHUNK * 32 + 8 * 32 + 64 * 33) * (int)sizeof(float);  // 28160 B
    cudaFuncSetAttribute(nsk_phase1, cudaFuncAttributeMaxDynamicSharedMemorySize, smem1);
    cudaFuncSetAttribute(nsk_phase2f, cudaFuncAttributeMaxDynamicSharedMemorySize, smem2);

    nsk_phase1<<<NCHUNK, 512, smem1>>>(X4, Y4);
    nsk_phase2f<<<NIJ / 32, 256, smem2>>>(out);
}

// round 11
// speedup vs baseline: 1.0472x; 1.0472x over previous
#include <cuda_runtime.h>
#include <cuda_bf16.h>
#include <cstdint>

#define TT 1024
#define BX 128
#define NIJ (BX * BX)
#define NCHUNK 146       // block 0: steps [0,8); block b>0: [7b+1, 7b+8)
#define BUFB 102400      // one double-buffer slot: A(51200) + B(51200) bytes

// scratch: local prefix products, layout [t][i*128+j]; 64 MB
__device__ float g_scratch[TT * NIJ];

__device__ __forceinline__ uint32_t smem_u32(const void* p) {
    uint32_t a;
    asm("{ .reg .u64 t; cvta.to.shared.u64 t, %1; cvt.u32.u64 %0, t; }"
        : "=r"(a) : "l"(p));
    return a;
}
__device__ __forceinline__ void ldsm_x4(uint32_t& r0, uint32_t& r1,
                                        uint32_t& r2, uint32_t& r3,
                                        uint32_t addr) {
    asm volatile("ldmatrix.sync.aligned.m8n8.x4.shared.b16 {%0,%1,%2,%3}, [%4];"
                 : "=r"(r0), "=r"(r1), "=r"(r2), "=r"(r3) : "r"(addr));
}
__device__ __forceinline__ void mma16816(float* c, const uint32_t* a,
                                         uint32_t b0, uint32_t b1) {
    asm volatile(
        "mma.sync.aligned.m16n8k16.row.col.f32.bf16.bf16.f32 "
        "{%0,%1,%2,%3}, {%4,%5,%6,%7}, {%8,%9}, {%0,%1,%2,%3};"
        : "+f"(c[0]), "+f"(c[1]), "+f"(c[2]), "+f"(c[3])
        : "r"(a[0]), "r"(a[1]), "r"(a[2]), "r"(a[3]), "r"(b0), "r"(b1));
}
__device__ __forceinline__ uint32_t bcat(__nv_bfloat16 a, __nv_bfloat16 b) {
    __nv_bfloat162 t = __halves2bfloat162(a, b);
    return *reinterpret_cast<uint32_t*>(&t);
}
__device__ __forceinline__ void pf_l2(const void* p) {
    asm volatile("prefetch.global.L2 [%0];" :: "l"(p));
}

// Phase 1 (HMMA): block b computes local prefix products over its steps.
// Per step, Z = (1023 dX) dY^T via bf16-split K=192 concat
//   A = [Xhi | Xhi | Xlo], B = [Yhi | Ylo | Yhi]  (one K-pass: hh + hl + lh).
// Double-buffered convert tiles -> ONE barrier per step; next-next step's
// rows prefetched to L2 (no register cost).
__global__ __launch_bounds__(512, 1)
void nsk_phase1(const float4* __restrict__ X4, const float4* __restrict__ Y4) {
    extern __shared__ char smc[];
    const uint32_t sb = smem_u32(smc);

    const int tid = threadIdx.x;
    const int wid = tid >> 5;
    const int lane = tid & 31;

    // conversion role
    const int crow = tid >> 2;           // 0..127
    const int cq = tid & 3;              // d-quad of 16
    const int gbase = crow * 16384 + cq * 4;
    // mma tile role
    const int m0 = (wid >> 2) * 32;
    const int n0 = (wid & 3) * 32;
    const int grp = lane >> 3, lrow = lane & 7;
    const uint32_t offA = (uint32_t)((lrow + 8 * (grp & 1)) * 400 + 16 * (grp >> 1));
    const uint32_t offB = (uint32_t)((lrow + 8 * (grp >> 1)) * 400 + 16 * (grp & 1));
    const int g = lane >> 2, tg = lane & 3;

    const int b = blockIdx.x;
    const int s_start = (b == 0) ? 0 : 7 * b + 1;
    const int s_end = 7 * b + 8;         // max 1023 at b=145

    float k[2][4][4];
#pragma unroll
    for (int a = 0; a < 2; a++)
#pragma unroll
        for (int c = 0; c < 4; c++)
#pragma unroll
            for (int e = 0; e < 4; e++) k[a][c][e] = 1.0f;

    // prologue: warm L2 with the first two time-rows
    pf_l2(X4 + gbase + s_start * 16);
    pf_l2(Y4 + gbase + s_start * 16);
    pf_l2(X4 + gbase + (s_start + 1) * 16);
    pf_l2(Y4 + gbase + (s_start + 1) * 16);

    int p = 0;
    for (int s = s_start; s < s_end; ++s) {
        // prefetch the row needed two steps ahead (row s+2)
        if (s + 2 <= s_end) {
            pf_l2(X4 + gbase + (s + 2) * 16);
            pf_l2(Y4 + gbase + (s + 2) * 16);
        }

        // ---- load diffs for step s, convert to bf16 hi/lo, STS into buf p
        {
            const int gb = gbase + s * 16;
            float fx[16], fy[16];
#pragma unroll
            for (int c = 0; c < 4; ++c) {
                float4 a0 = X4[gb + c], a1 = X4[gb + 16 + c];
                fx[4 * c + 0] = (a1.x - a0.x) * 1023.0f;
                fx[4 * c + 1] = (a1.y - a0.y) * 1023.0f;
                fx[4 * c + 2] = (a1.z - a0.z) * 1023.0f;
                fx[4 * c + 3] = (a1.w - a0.w) * 1023.0f;
                float4 b0 = Y4[gb + c], b1 = Y4[gb + 16 + c];
                fy[4 * c + 0] = b1.x - b0.x;
                fy[4 * c + 1] = b1.y - b0.y;
                fy[4 * c + 2] = b1.z - b0.z;
                fy[4 * c + 3] = b1.w - b0.w;
            }
            uint32_t xh[8], xl[8], yh[8], yl[8];
#pragma unroll
            for (int m = 0; m < 8; ++m) {
                float u = fx[2 * m], v = fx[2 * m + 1];
                __nv_bfloat16 uh = __float2bfloat16_rn(u);
                __nv_bfloat16 vh = __float2bfloat16_rn(v);
                xh[m] = bcat(uh, vh);
                xl[m] = bcat(__float2bfloat16_rn(u - __bfloat162float(uh)),
                             __float2bfloat16_rn(v - __bfloat162float(vh)));
                float pp = fy[2 * m], q = fy[2 * m + 1];
                __nv_bfloat16 ph = __float2bfloat16_rn(pp);
                __nv_bfloat16 qh = __float2bfloat16_rn(q);
                yh[m] = bcat(ph, qh);
                yl[m] = bcat(__float2bfloat16_rn(pp - __bfloat162float(ph)),
                             __float2bfloat16_rn(q - __bfloat162float(qh)));
            }
            char* bufc = smc + p * BUFB;
            char* pa = bufc + crow * 400 + cq * 32;
            ((uint4*)pa)[0] = ((uint4*)xh)[0];
            ((uint4*)(pa + 16))[0] = ((uint4*)xh)[1];
            ((uint4*)(pa + 128))[0] = ((uint4*)xh)[0];      // Xhi copy 2
            ((uint4*)(pa + 144))[0] = ((uint4*)xh)[1];
            ((uint4*)(pa + 256))[0] = ((uint4*)xl)[0];      // Xlo
            ((uint4*)(pa + 272))[0] = ((uint4*)xl)[1];
            char* pb = bufc + 51200 + crow * 400 + cq * 32;
            ((uint4*)pb)[0] = ((uint4*)yh)[0];              // Yhi
            ((uint4*)(pb + 16))[0] = ((uint4*)yh)[1];
            ((uint4*)(pb + 128))[0] = ((uint4*)yl)[0];      // Ylo
            ((uint4*)(pb + 144))[0] = ((uint4*)yl)[1];
            ((uint4*)(pb + 256))[0] = ((uint4*)yh)[0];      // Yhi copy 2
            ((uint4*)(pb + 272))[0] = ((uint4*)yh)[1];
        }

        __syncthreads();   // buf p visible; all reads of buf p^1 (step s-1 MMA) done

        // ---- 12 k-chunks of 16 over K=192
        const uint32_t aA = sb + p * BUFB;
        const uint32_t aB = aA + 51200;
        float cacc[2][4][4];
#pragma unroll
        for (int mf = 0; mf < 2; mf++)
#pragma unroll
            for (int nf = 0; nf < 4; nf++)
#pragma unroll
                for (int e = 0; e < 4; e++) cacc[mf][nf][e] = 0.0f;

#pragma unroll
        for (int kc = 0; kc < 12; ++kc) {
            const uint32_t kb = kc * 32;
            uint32_t af0[4], af1[4], b0r[4], b1r[4];
            ldsm_x4(af0[0], af0[1], af0[2], af0[3], aA + m0 * 400 + kb + offA);
            ldsm_x4(af1[0], af1[1], af1[2], af1[3], aA + (m0 + 16) * 400 + kb + offA);
            ldsm_x4(b0r[0], b0r[1], b0r[2], b0r[3], aB + n0 * 400 + kb + offB);
            ldsm_x4(b1r[0], b1r[1], b1r[2], b1r[3], aB + (n0 + 16) * 400 + kb + offB);
            mma16816(cacc[0][0], af0, b0r[0], b0r[1]);
            mma16816(cacc[0][1], af0, b0r[2], b0r[3]);
            mma16816(cacc[0][2], af0, b1r[0], b1r[1]);
            mma16816(cacc[0][3], af0, b1r[2], b1r[3]);
            mma16816(cacc[1][0], af1, b0r[0], b0r[1]);
            mma16816(cacc[1][1], af1, b0r[2], b0r[3]);
            mma16816(cacc[1][2], af1, b1r[0], b1r[1]);
            mma16816(cacc[1][3], af1, b1r[2], b1r[3]);
        }

        // ---- epilogue: k *= (1+z); float2 stores, scratch[t][i*128+j]
        float* base = g_scratch + (size_t)(s + 1) * NIJ;
#pragma unroll
        for (int mf = 0; mf < 2; mf++) {
#pragma unroll
            for (int nf = 0; nf < 4; nf++) {
                const int i0 = m0 + mf * 16 + g;
                const int j = n0 + nf * 8 + tg * 2;
                float* c4 = cacc[mf][nf];
                float* kk = k[mf][nf];
                float k0 = fmaf(c4[0], kk[0], kk[0]);
                float k1 = fmaf(c4[1], kk[1], kk[1]);
                float k2 = fmaf(c4[2], kk[2], kk[2]);
                float k3 = fmaf(c4[3], kk[3], kk[3]);
                kk[0] = k0; kk[1] = k1; kk[2] = k2; kk[3] = k3;
                *(float2*)(base + i0 * BX + j) = make_float2(k0, k1);
                *(float2*)(base + (i0 + 8) * BX + j) = make_float2(k2, k3);
            }
        }
        p ^= 1;
    }
}

// Phase 2 (fused): one block per 32-ij strip. Chunk c's last written t is
// e = 7c+8; owner of t>=1 is c = (t-2)/7 (trunc; t=1 -> 0).
__global__ __launch_bounds__(256, 8)
void nsk_phase2f(float* __restrict__ out) {
    extern __shared__ float sm[];
    float* cend = sm;                    // [146][32] -> exclusive scales
    float* qp = sm + NCHUNK * 32;        // [8][32]
    float* tile = qp + 8 * 32;           // [64][33]

    const int tid = threadIdx.x;
    const int lane = tid & 31;
    const int q = tid >> 5;              // 0..7
    const int lane64 = tid & 63;
    const int colg = tid >> 6;           // 0..3
    const int ij0 = blockIdx.x * 32;

#pragma unroll
    for (int cc = 0; cc < 19; cc++) {
        const int c = q + 8 * cc;
        if (c < NCHUNK) {
            const int e = 7 * c + 8;
            cend[c * 32 + lane] = g_scratch[(size_t)e * NIJ + ij0 + lane];
        }
    }
    __syncthreads();
    {
        float p = 1.0f;
#pragma unroll 1
        for (int cc = 0; cc < 19; cc++) {
            const int c = 19 * q + cc;
            if (c < NCHUNK) {
                const float v = cend[c * 32 + lane];
                cend[c * 32 + lane] = p;
                p *= v;
            }
        }
        qp[q * 32 + lane] = p;
    }
    __syncthreads();
    if (q > 0) {
        float off = qp[lane];
#pragma unroll
        for (int w = 1; w < 7; w++)
            if (q > w) off *= qp[w * 32 + lane];
#pragma unroll 1
        for (int cc = 0; cc < 19; cc++) {
            const int c = 19 * q + cc;
            if (c < NCHUNK) cend[c * 32 + lane] *= off;
        }
    }
    __syncthreads();

#pragma unroll 1
    for (int ti = 0; ti < 16; ti++) {
        const int t0 = ti * 64;
#pragma unroll
        for (int rr = 0; rr < 8; rr++) {
            const int r = q + 8 * rr;
            const int t = t0 + r;
            if (t == 0) {
                tile[r * 33 + lane] = 1.0f;
            } else {
                const int c = (t - 2) / 7;   // t=1 -> 0
                const float v = g_scratch[(size_t)t * NIJ + ij0 + lane];
                tile[r * 33 + lane] = v * cend[c * 32 + lane];
            }
        }
        __syncthreads();
#pragma unroll
        for (int cc = 0; cc < 8; cc++) {
            const int col = colg + 4 * cc;
            out[(size_t)(ij0 + col) * TT + t0 + lane64] = tile[lane64 * 33 + col];
        }
        __syncthreads();
    }
}

extern "C" void kernel_launch(void* const* d_in, const int* in_sizes, int n_in,
                              void* d_out, int out_size) {
    const float4* X4 = (const float4*)d_in[0];
    const float4* Y4 = (const float4*)d_in[1];
    float* out = (float*)d_out;

    const int smem1 = 2 * BUFB;                                               // 204800 B
    const int smem2 = (NCHUNK * 32 + 8 * 32 + 64 * 33) * (int)sizeof(float);  // 28160 B
    cudaFuncSetAttribute(nsk_phase1, cudaFuncAttributeMaxDynamicSharedMemorySize, smem1);
    cudaFuncSetAttribute(nsk_phase2f, cudaFuncAttributeMaxDynamicSharedMemorySize, smem2);

    nsk_phase1<<<NCHUNK, 512, smem1>>>(X4, Y4);
    nsk_phase2f<<<NIJ / 32, 256, smem2>>>(out);
}

// round 12
// speedup vs baseline: 1.1359x; 1.0847x over previous
#include <cuda_runtime.h>
#include <cuda_bf16.h>
#include <cstdint>

#define TT 1024
#define BX 128
#define NIJ (BX * BX)
#define NCHUNK 146       // block 0: steps [0,8); block b>0: [7b+1, 7b+8)
#define SAB 200          // smem bf16 row stride (400 B)

// scratch: local prefix products, layout [t][i*128+j]; 64 MB
__device__ float g_scratch[TT * NIJ];

__device__ __forceinline__ uint32_t smem_u32(const void* p) {
    uint32_t a;
    asm("{ .reg .u64 t; cvta.to.shared.u64 t, %1; cvt.u32.u64 %0, t; }"
        : "=r"(a) : "l"(p));
    return a;
}
__device__ __forceinline__ void ldsm_x4(uint32_t& r0, uint32_t& r1,
                                        uint32_t& r2, uint32_t& r3,
                                        uint32_t addr) {
    asm volatile("ldmatrix.sync.aligned.m8n8.x4.shared.b16 {%0,%1,%2,%3}, [%4];"
                 : "=r"(r0), "=r"(r1), "=r"(r2), "=r"(r3) : "r"(addr));
}
__device__ __forceinline__ void mma16816(float* c, const uint32_t* a,
                                         uint32_t b0, uint32_t b1) {
    asm volatile(
        "mma.sync.aligned.m16n8k16.row.col.f32.bf16.bf16.f32 "
        "{%0,%1,%2,%3}, {%4,%5,%6,%7}, {%8,%9}, {%0,%1,%2,%3};"
        : "+f"(c[0]), "+f"(c[1]), "+f"(c[2]), "+f"(c[3])
        : "r"(a[0]), "r"(a[1]), "r"(a[2]), "r"(a[3]), "r"(b0), "r"(b1));
}
__device__ __forceinline__ uint32_t bcat(__nv_bfloat16 a, __nv_bfloat16 b) {
    __nv_bfloat162 t = __halves2bfloat162(a, b);
    return *reinterpret_cast<uint32_t*>(&t);
}

// Phase 1 (HMMA): block b computes local prefix products over steps
// [7b+1, 7b+8) (block 0: [0,8)). Per step, Z = (1023 dX) dY^T via bf16-split
// K=192 concat A=[Xhi|Xhi|Xlo], B=[Yhi|Ylo|Yhi] (hh + hl + lh in one pass).
// Single smem buffer (102 KB) keeps ~125 KB L1D so row s+1 re-hits L1 at
// step s+1. 16 warps in a 4x4 grid, 32x32 C tile each.
__global__ __launch_bounds__(512, 1)
void nsk_phase1(const float4* __restrict__ X4, const float4* __restrict__ Y4) {
    extern __shared__ __nv_bfloat16 smb[];
    __nv_bfloat16* sA = smb;                 // [128][SAB]
    __nv_bfloat16* sB = smb + 128 * SAB;     // [128][SAB]
    const uint32_t aA = smem_u32(sA);
    const uint32_t aB = smem_u32(sB);

    const int tid = threadIdx.x;
    const int wid = tid >> 5;
    const int lane = tid & 31;

    // conversion role
    const int crow = tid >> 2;           // 0..127
    const int cq = tid & 3;              // d-quad of 16
    // mma tile role
    const int m0 = (wid >> 2) * 32;
    const int n0 = (wid & 3) * 32;
    const int grp = lane >> 3, lrow = lane & 7;
    const uint32_t offA = (uint32_t)((lrow + 8 * (grp & 1)) * 400 + 16 * (grp >> 1));
    const uint32_t offB = (uint32_t)((lrow + 8 * (grp >> 1)) * 400 + 16 * (grp & 1));
    const int g = lane >> 2, tg = lane & 3;

    const int b = blockIdx.x;
    const int s_start = (b == 0) ? 0 : 7 * b + 1;
    const int s_end = 7 * b + 8;         // max 1023 at b=145

    float k[2][4][4];
#pragma unroll
    for (int a = 0; a < 2; a++)
#pragma unroll
        for (int c = 0; c < 4; c++)
#pragma unroll
            for (int e = 0; e < 4; e++) k[a][c][e] = 1.0f;

    for (int s = s_start; s < s_end; ++s) {
        __syncthreads();   // all warps done reading smem from previous step

        // ---- convert: 16 d-values per thread -> hi/lo bf16, K=192 layout
        {
            const int gb = crow * 16384 + s * 16 + cq * 4;
            float fx[16], fy[16];
#pragma unroll
            for (int c = 0; c < 4; ++c) {
                float4 a0 = X4[gb + c], a1 = X4[gb + 16 + c];
                fx[4 * c + 0] = (a1.x - a0.x) * 1023.0f;
                fx[4 * c + 1] = (a1.y - a0.y) * 1023.0f;
                fx[4 * c + 2] = (a1.z - a0.z) * 1023.0f;
                fx[4 * c + 3] = (a1.w - a0.w) * 1023.0f;
                float4 b0 = Y4[gb + c], b1 = Y4[gb + 16 + c];
                fy[4 * c + 0] = b1.x - b0.x;
                fy[4 * c + 1] = b1.y - b0.y;
                fy[4 * c + 2] = b1.z - b0.z;
                fy[4 * c + 3] = b1.w - b0.w;
            }
            uint32_t xh[8], xl[8], yh[8], yl[8];
#pragma unroll
            for (int m = 0; m < 8; ++m) {
                float u = fx[2 * m], v = fx[2 * m + 1];
                __nv_bfloat16 uh = __float2bfloat16_rn(u);
                __nv_bfloat16 vh = __float2bfloat16_rn(v);
                xh[m] = bcat(uh, vh);
                xl[m] = bcat(__float2bfloat16_rn(u - __bfloat162float(uh)),
                             __float2bfloat16_rn(v - __bfloat162float(vh)));
                float p = fy[2 * m], q = fy[2 * m + 1];
                __nv_bfloat16 ph = __float2bfloat16_rn(p);
                __nv_bfloat16 qh = __float2bfloat16_rn(q);
                yh[m] = bcat(ph, qh);
                yl[m] = bcat(__float2bfloat16_rn(p - __bfloat162float(ph)),
                             __float2bfloat16_rn(q - __bfloat162float(qh)));
            }
            char* pa = (char*)sA + crow * 400 + cq * 32;
            ((uint4*)pa)[0] = ((uint4*)xh)[0];
            ((uint4*)(pa + 16))[0] = ((uint4*)xh)[1];
            ((uint4*)(pa + 128))[0] = ((uint4*)xh)[0];      // Xhi copy 2
            ((uint4*)(pa + 144))[0] = ((uint4*)xh)[1];
            ((uint4*)(pa + 256))[0] = ((uint4*)xl)[0];      // Xlo
            ((uint4*)(pa + 272))[0] = ((uint4*)xl)[1];
            char* pb = (char*)sB + crow * 400 + cq * 32;
            ((uint4*)pb)[0] = ((uint4*)yh)[0];              // Yhi
            ((uint4*)(pb + 16))[0] = ((uint4*)yh)[1];
            ((uint4*)(pb + 128))[0] = ((uint4*)yl)[0];      // Ylo
            ((uint4*)(pb + 144))[0] = ((uint4*)yl)[1];
            ((uint4*)(pb + 256))[0] = ((uint4*)yh)[0];      // Yhi copy 2
            ((uint4*)(pb + 272))[0] = ((uint4*)yh)[1];
        }
        __syncthreads();

        // ---- 12 k-chunks of 16 over the K=192 concat
        float cacc[2][4][4];
#pragma unroll
        for (int mf = 0; mf < 2; mf++)
#pragma unroll
            for (int nf = 0; nf < 4; nf++)
#pragma unroll
                for (int e = 0; e < 4; e++) cacc[mf][nf][e] = 0.0f;

#pragma unroll
        for (int kc = 0; kc < 12; ++kc) {
            const uint32_t kb = kc * 32;
            uint32_t af0[4], af1[4], b0r[4], b1r[4];
            ldsm_x4(af0[0], af0[1], af0[2], af0[3], aA + m0 * 400 + kb + offA);
            ldsm_x4(af1[0], af1[1], af1[2], af1[3], aA + (m0 + 16) * 400 + kb + offA);
            ldsm_x4(b0r[0], b0r[1], b0r[2], b0r[3], aB + n0 * 400 + kb + offB);
            ldsm_x4(b1r[0], b1r[1], b1r[2], b1r[3], aB + (n0 + 16) * 400 + kb + offB);
            mma16816(cacc[0][0], af0, b0r[0], b0r[1]);
            mma16816(cacc[0][1], af0, b0r[2], b0r[3]);
            mma16816(cacc[0][2], af0, b1r[0], b1r[1]);
            mma16816(cacc[0][3], af0, b1r[2], b1r[3]);
            mma16816(cacc[1][0], af1, b0r[0], b0r[1]);
            mma16816(cacc[1][1], af1, b0r[2], b0r[3]);
            mma16816(cacc[1][2], af1, b1r[0], b1r[1]);
            mma16816(cacc[1][3], af1, b1r[2], b1r[3]);
        }

        // ---- epilogue: k *= (1+z); float2 stores, scratch[t][i*128+j]
        float* base = g_scratch + (size_t)(s + 1) * NIJ;
#pragma unroll
        for (int mf = 0; mf < 2; mf++) {
#pragma unroll
            for (int nf = 0; nf < 4; nf++) {
                const int i0 = m0 + mf * 16 + g;
                const int j = n0 + nf * 8 + tg * 2;
                float* c4 = cacc[mf][nf];
                float* kk = k[mf][nf];
                float k0 = fmaf(c4[0], kk[0], kk[0]);
                float k1 = fmaf(c4[1], kk[1], kk[1]);
                float k2 = fmaf(c4[2], kk[2], kk[2]);
                float k3 = fmaf(c4[3], kk[3], kk[3]);
                kk[0] = k0; kk[1] = k1; kk[2] = k2; kk[3] = k3;
                *(float2*)(base + i0 * BX + j) = make_float2(k0, k1);
                *(float2*)(base + (i0 + 8) * BX + j) = make_float2(k2, k3);
            }
        }
    }
}

// Phase 2 (fused): one block per 32-ij strip. Chunk c's last written t is
// e = 7c+8; owner of t>=1 is c = (t-2)/7 (trunc; t=1 -> 0).
__global__ __launch_bounds__(256, 8)
void nsk_phase2f(float* __restrict__ out) {
    extern __shared__ float sm[];
    float* cend = sm;                    // [146][32] -> exclusive scales
    float* qp = sm + NCHUNK * 32;        // [8][32]
    float* tile = qp + 8 * 32;           // [64][33]

    const int tid = threadIdx.x;
    const int lane = tid & 31;
    const int q = tid >> 5;              // 0..7
    const int lane64 = tid & 63;
    const int colg = tid >> 6;           // 0..3
    const int ij0 = blockIdx.x * 32;

#pragma unroll
    for (int cc = 0; cc < 19; cc++) {
        const int c = q + 8 * cc;
        if (c < NCHUNK) {
            const int e = 7 * c + 8;
            cend[c * 32 + lane] = g_scratch[(size_t)e * NIJ + ij0 + lane];
        }
    }
    __syncthreads();
    {
        float p = 1.0f;
#pragma unroll 1
        for (int cc = 0; cc < 19; cc++) {
            const int c = 19 * q + cc;
            if (c < NCHUNK) {
                const float v = cend[c * 32 + lane];
                cend[c * 32 + lane] = p;
                p *= v;
            }
        }
        qp[q * 32 + lane] = p;
    }
    __syncthreads();
    if (q > 0) {
        float off = qp[lane];
#pragma unroll
        for (int w = 1; w < 7; w++)
            if (q > w) off *= qp[w * 32 + lane];
#pragma unroll 1
        for (int cc = 0; cc < 19; cc++) {
            const int c = 19 * q + cc;
            if (c < NCHUNK) cend[c * 32 + lane] *= off;
        }
    }
    __syncthreads();

#pragma unroll 1
    for (int ti = 0; ti < 16; ti++) {
        const int t0 = ti * 64;
#pragma unroll
        for (int rr = 0; rr < 8; rr++) {
            const int r = q + 8 * rr;
            const int t = t0 + r;
            if (t == 0) {
                tile[r * 33 + lane] = 1.0f;
            } else {
                const int c = (t - 2) / 7;   // t=1 -> 0
                const float v = g_scratch[(size_t)t * NIJ + ij0 + lane];
                tile[r * 33 + lane] = v * cend[c * 32 + lane];
            }
        }
        __syncthreads();
#pragma unroll
        for (int cc = 0; cc < 8; cc++) {
            const int col = colg + 4 * cc;
            out[(size_t)(ij0 + col) * TT + t0 + lane64] = tile[lane64 * 33 + col];
        }
        __syncthreads();
    }
}

extern "C" void kernel_launch(void* const* d_in, const int* in_sizes, int n_in,
                              void* d_out, int out_size) {
    const float4* X4 = (const float4*)d_in[0];
    const float4* Y4 = (const float4*)d_in[1];
    float* out = (float*)d_out;

    const int smem1 = 2 * 128 * SAB * (int)sizeof(__nv_bfloat16);             // 102400 B
    const int smem2 = (NCHUNK * 32 + 8 * 32 + 64 * 33) * (int)sizeof(float);  // 28160 B
    cudaFuncSetAttribute(nsk_phase1, cudaFuncAttributeMaxDynamicSharedMemorySize, smem1);
    cudaFuncSetAttribute(nsk_phase2f, cudaFuncAttributeMaxDynamicSharedMemorySize, smem2);

    nsk_phase1<<<NCHUNK, 512, smem1>>>(X4, Y4);
    nsk_phase2f<<<NIJ / 32, 256, smem2>>>(out);
}